// round 8
// baseline (speedup 1.0000x reference)
#include <cuda_runtime.h>
#include <cstdint>

#define BB 8
#define CC 512
#define NNODES 2048
#define TT 24

#define K1_CT    128    // c-tile per block
#define K1_NC    8      // n per chunk
#define K1_PITCH 196    // smem floats per c-row (8*24=192 + 4 pad; 16B-aligned, bank-spread)
#define K1_SMEM  ((K1_CT*K1_PITCH + 192) * 4)   // tile + f1stage bytes

typedef unsigned long long ull;

// ---------------- scratch (static device arrays; no allocation) ----------------
__device__ float g_f1  [BB*TT*NNODES];   // f1[b][t][n]          (atomically accumulated)
__device__ float g_f1c [BB*TT*NNODES];   // dilated conv of f1
__device__ float g_f2  [BB*CC*TT];       // f2[b][c][t]          (atomically accumulated)
__device__ float g_f2cT[BB*TT*CC];       // f2c transposed [b][t][c]   (atomically accumulated)
__device__ float g_g   [BB*TT*CC];       // g[b][t][c] = f1c @ w       (atomically accumulated)
__device__ float g_s   [BB*TT*TT];       // sigmoid attention matrix

// ---------------- packed f32x2 helpers ----------------
__device__ __forceinline__ ull fma2(ull a, ull b, ull c){
    ull d;
    asm("fma.rn.f32x2 %0, %1, %2, %3;" : "=l"(d) : "l"(a), "l"(b), "l"(c));
    return d;
}
__device__ __forceinline__ ull add2(ull a, ull b){
    ull d;
    asm("add.rn.f32x2 %0, %1, %2;" : "=l"(d) : "l"(a), "l"(b));
    return d;
}
__device__ __forceinline__ ull pack2(float f){
    ull r;
    asm("mov.b64 %0, {%1, %1};" : "=l"(r) : "f"(f));
    return r;
}
__device__ __forceinline__ float2 unpk2(ull v){
    float2 f;
    asm("mov.b64 {%0, %1}, %2;" : "=f"(f.x), "=f"(f.y) : "l"(v));
    return f;
}

// ---------------- K0: zero accumulated scratch ----------------
__global__ void k0_zero(){
    int idx = blockIdx.x * 256 + threadIdx.x;
    if (idx < BB*TT*NNODES) g_f1[idx] = 0.0f;
    if (idx < BB*CC*TT){
        g_f2  [idx] = 0.0f;
        g_f2cT[idx] = 0.0f;
        g_g   [idx] = 0.0f;
    }
}

// ---------------- K1: fused dual weighted reduction over seq (smem-staged) ----------------
// grid = 8b x 4ct x 8ns = 256 blocks, block = 192 (6 warps x t-quad; lane covers 4 c).
// Stages (128c x 8n x 24t) tiles coalesced, computes both reductions from smem.
__global__ void __launch_bounds__(192, 2)
k1_reduce(const float* __restrict__ seq, const float* __restrict__ w1, const float* __restrict__ w2){
    extern __shared__ float sm[];
    float* tile = sm;                      // [128][K1_PITCH]
    float* f1st = sm + K1_CT*K1_PITCH;     // [8 nn][24 t]

    const int blk  = blockIdx.x;
    const int b    = blk >> 5;             // 0..7
    const int ct   = (blk >> 3) & 3;       // c-tile 0..3
    const int ns   = blk & 7;              // n-sweep 0..7
    const int tid  = threadIdx.x;
    const int w    = tid >> 5;             // t-quad 0..5
    const int lane = tid & 31;

    // staging map: 48 threads share one j (float4 within the 192-float c-row);
    // thread covers c = c0s + 4*k for k = 0..31  (full 128 rows).
    const int j    = tid % 48;             // float4 index within c-row
    const int c0s  = tid / 48;             // 0..3
    const int jf   = j * 4;
    const float* seqbase = seq + ((size_t)(b*CC + ct*K1_CT) * NNODES) * TT;

    ull w1p[4];
#pragma unroll
    for (int kk = 0; kk < 4; ++kk) w1p[kk] = pack2(w1[ct*K1_CT + lane + 32*kk]);

    ull acc[4][2];
#pragma unroll
    for (int kk = 0; kk < 4; ++kk){ acc[kk][0] = 0ull; acc[kk][1] = 0ull; }

    const int nbase = ns * 256;

    for (int ch = 0; ch < 32; ++ch){
        const int n0 = nbase + ch*K1_NC;
        const float wv2 = w2[n0 + (lane & 7)];
        const float* gch = seqbase + (size_t)n0 * TT + jf;    // + c*49152

        // ---- stage tile (coalesced): 32 float4 per thread, batched 8-wide for MLP ----
#pragma unroll
        for (int batch = 0; batch < 4; ++batch){
            float4 v[8];
#pragma unroll
            for (int u = 0; u < 8; ++u){
                int c = c0s + 4*(batch*8 + u);
                v[u] = *reinterpret_cast<const float4*>(gch + (size_t)c * (NNODES*TT));
            }
#pragma unroll
            for (int u = 0; u < 8; ++u){
                int c = c0s + 4*(batch*8 + u);
                *reinterpret_cast<float4*>(&tile[c*K1_PITCH + jf]) = v[u];
            }
        }
        __syncthreads();

        // ---- compute from smem ----
#pragma unroll
        for (int nn = 0; nn < K1_NC; ++nn){
            const ull w2p = pack2(__shfl_sync(0xffffffffu, wv2, nn));
            ull p0 = 0ull, p1 = 0ull;
#pragma unroll
            for (int kk = 0; kk < 4; ++kk){
                const ull* xp = reinterpret_cast<const ull*>(
                    &tile[(lane + 32*kk)*K1_PITCH + nn*24 + w*4]);
                ull x0 = xp[0], x1 = xp[1];
                p0 = fma2(w1p[kk], x0, p0);
                p1 = fma2(w1p[kk], x1, p1);
                acc[kk][0] = fma2(w2p, x0, acc[kk][0]);
                acc[kk][1] = fma2(w2p, x1, acc[kk][1]);
            }
#pragma unroll
            for (int off = 16; off > 0; off >>= 1){
                p0 = add2(p0, __shfl_xor_sync(0xffffffffu, p0, off));
                p1 = add2(p1, __shfl_xor_sync(0xffffffffu, p1, off));
            }
            if (lane == 0){
                float2 a = unpk2(p0), d = unpk2(p1);
                *reinterpret_cast<float4*>(&f1st[nn*24 + w*4]) = make_float4(a.x, a.y, d.x, d.y);
            }
        }
        __syncthreads();

        // ---- flush f1 partial (192 floats, one per thread) ----
        {
            int nn = tid / 24, t = tid % 24;
            atomicAdd(&g_f1[((size_t)b*TT + t)*NNODES + n0 + nn], f1st[nn*24 + t]);
        }
    }

    // ---- flush f2 (register-resident for the whole n-sweep) ----
#pragma unroll
    for (int kk = 0; kk < 4; ++kk){
        int c = ct*K1_CT + lane + 32*kk;
        float* o = g_f2 + ((size_t)b*CC + c)*TT + w*4;
        float2 a = unpk2(acc[kk][0]), d = unpk2(acc[kk][1]);
        atomicAdd(o + 0, a.x);
        atomicAdd(o + 1, a.y);
        atomicAdd(o + 2, d.x);
        atomicAdd(o + 3, d.y);
    }
}

// ---------------- K2a: dilated conv of f1 over the n axis ----------------
__global__ void k2a_conv1(const float* __restrict__ Wd1){
    const int b  = blockIdx.x >> 4;
    const int n0 = (blockIdx.x & 15) * 128;
    __shared__ float s1[TT][130];
    __shared__ float sw[TT][48];
    for (int idx = threadIdx.x; idx < TT*48; idx += 256)
        ((float*)sw)[idx] = Wd1[idx];
    for (int idx = threadIdx.x; idx < TT*130; idx += 256){
        int i = idx / 130, jj = idx % 130;
        int n = n0 + jj - 1;
        s1[i][jj] = (n >= 0 && n < NNODES) ? g_f1[((size_t)b*TT + i)*NNODES + n] : 0.0f;
    }
    __syncthreads();
#pragma unroll
    for (int u = 0; u < 12; ++u){
        int idx = threadIdx.x + u*256;
        int t = idx >> 7, nl = idx & 127;
        float acc = 0.0f;
#pragma unroll
        for (int i = 0; i < TT; ++i)
            acc += s1[i][nl] * sw[t][2*i] + s1[i][nl+2] * sw[t][2*i+1];
        g_f1c[((size_t)b*TT + t)*NNODES + n0 + nl] = acc;
    }
}

// ---------------- K2b: dilated conv of f2 over the t axis (K-split GEMM) ----------------
__global__ void __launch_bounds__(256) k2b_conv2(const float* __restrict__ Wd2){
    const int o0 = (blockIdx.x & 15) * 32;
    const int i0 = (blockIdx.x >> 4) * 32;
    const int tid   = threadIdx.x;
    const int olane = tid & 31;
    const int b     = tid >> 5;

    __shared__ __align__(16) float  sf[32][8][26];
    __shared__ float2 sw2[32][33];

    {
        int i = tid >> 3, bb = tid & 7;
        sf[i][bb][0] = 0.0f; sf[i][bb][25] = 0.0f;
    }
#pragma unroll
    for (int u = 0; u < 24; ++u){
        int idx = tid + u*256;
        int i = idx / 192, r = idx % 192;
        int bb = r / 24, t = r % 24;
        sf[i][bb][t+1] = g_f2[((size_t)bb*CC + i0 + i)*TT + t];
    }
    const float2* wsrc = reinterpret_cast<const float2*>(Wd2);
#pragma unroll
    for (int u = 0; u < 4; ++u){
        int idx = tid + u*256;
        int oo = idx >> 5, iz = idx & 31;
        sw2[oo][iz] = wsrc[(size_t)(o0+oo)*CC + i0 + iz];
    }
    __syncthreads();

    ull acc[12];
#pragma unroll
    for (int u = 0; u < 12; ++u) acc[u] = 0ull;
#pragma unroll 4
    for (int iz = 0; iz < 32; ++iz){
        float2 wv = sw2[olane][iz];
        ull wx = pack2(wv.x), wy = pack2(wv.y);
        const ull* R = reinterpret_cast<const ull*>(&sf[iz][b][0]);
#pragma unroll
        for (int u = 0; u < 12; ++u){
            acc[u] = fma2(wx, R[u], acc[u]);
            acc[u] = fma2(wy, R[u+1], acc[u]);
        }
    }
    float* ob = g_f2cT + (size_t)b*TT*CC + o0 + olane;
#pragma unroll
    for (int u = 0; u < 12; ++u){
        float2 r = unpk2(acc[u]);
        atomicAdd(&ob[(2*u  )*CC], r.x);
        atomicAdd(&ob[(2*u+1)*CC], r.y);
    }
}

// ---------------- K2c: g[b,t,c] += sum_n f1c[b,t,n] * w[n,c]  (K-split x4) ----------------
__global__ void __launch_bounds__(192) k2c_gemm(const float* __restrict__ w){
    const int b  = blockIdx.x >> 6;
    const int c0 = ((blockIdx.x >> 2) & 15) * 32;
    const int ks = blockIdx.x & 3;
    const int tid = threadIdx.x;
    const int tq = tid >> 3;
    const int cq = tid & 7;
    __shared__ __align__(16) float sA[TT*129];
    __shared__ __align__(16) float sB[128*36];
    ull acc[2] = {0ull, 0ull};
    for (int kt = 0; kt < 4; ++kt){
        const int n0 = ks*512 + kt*128;
        for (int idx = tid; idx < 3072; idx += 192){
            int r = idx >> 7, col = idx & 127;
            sA[r*129 + col] = g_f1c[((size_t)b*TT + r)*NNODES + n0 + col];
        }
        for (int idx = tid; idx < 4096; idx += 192){
            int r = idx >> 5, cl = idx & 31;
            sB[r*36 + cl] = w[(size_t)(n0 + r)*CC + c0 + cl];
        }
        __syncthreads();
#pragma unroll 8
        for (int r = 0; r < 128; ++r){
            ull a0 = pack2(sA[tq*129 + r]);
            ulonglong2 bv = *reinterpret_cast<const ulonglong2*>(&sB[r*36 + cq*4]);
            acc[0] = fma2(a0, bv.x, acc[0]);
            acc[1] = fma2(a0, bv.y, acc[1]);
        }
        __syncthreads();
    }
    float2 r0 = unpk2(acc[0]), r1 = unpk2(acc[1]);
    float* o0 = g_g + ((size_t)b*TT + tq)*CC + c0 + cq*4;
    atomicAdd(&o0[0], r0.x);
    atomicAdd(&o0[1], r0.y);
    atomicAdd(&o0[2], r1.x);
    atomicAdd(&o0[3], r1.y);
}

// ---------------- K2d1: s[b,j,k] = sigmoid(g[b,j,:] . f2cT[b,k,:] + bias) ----------------
__global__ void __launch_bounds__(128) k2d1_attn(const float* __restrict__ bbias){
    const int b = blockIdx.x / 24;
    const int jj = blockIdx.x % 24;
    const int tid  = threadIdx.x;
    const int wrp  = tid >> 5;
    const int lane = tid & 31;
    __shared__ __align__(16) float sg[CC];
    const float* grow = g_g + ((size_t)b*TT + jj)*CC;
#pragma unroll
    for (int u = 0; u < 4; ++u) sg[tid + u*128] = grow[tid + u*128];
    __syncthreads();
    const ull* sg2 = reinterpret_cast<const ull*>(sg);
    const ull* f0  = reinterpret_cast<const ull*>(g_f2cT + ((size_t)b*TT + wrp*6)*CC);
    ull acc[6] = {0ull,0ull,0ull,0ull,0ull,0ull};
#pragma unroll
    for (int it = 0; it < 8; ++it){
        ull gv = sg2[lane + it*32];
#pragma unroll
        for (int kk = 0; kk < 6; ++kk)
            acc[kk] = fma2(f0[(size_t)kk*256 + lane + it*32], gv, acc[kk]);
    }
#pragma unroll
    for (int kk = 0; kk < 6; ++kk)
#pragma unroll
        for (int off = 16; off > 0; off >>= 1)
            acc[kk] = add2(acc[kk], __shfl_xor_sync(0xffffffffu, acc[kk], off));
    if (lane < 6){
        int k = wrp*6 + lane;
        float2 aa = unpk2(acc[lane]);
        float sv = aa.x + aa.y + bbias[jj*TT + k];
        g_s[((size_t)b*TT + jj)*TT + k] = 1.0f/(1.0f + __expf(-sv));
    }
}

// ---------------- K2d2: l = v @ s; BN + mask + softmax (single block) ----------------
__global__ void k2d2_final(const float* __restrict__ v, const float* __restrict__ gamma,
                           const float* __restrict__ beta, float* __restrict__ out){
    const int tid = threadIdx.x;
    __shared__ float ss[BB][TT][TT];
    __shared__ float sv[TT][TT];
    __shared__ float sl[192][25];
    __shared__ float smean[TT], sinv[TT];
    for (int idx = tid; idx < BB*TT*TT; idx += 192) ((float*)ss)[idx] = g_s[idx];
    for (int idx = tid; idx < TT*TT;   idx += 192) ((float*)sv)[idx] = v[idx];
    __syncthreads();
    const int b = tid / TT, i = tid % TT;
    float l[TT];
#pragma unroll
    for (int k = 0; k < TT; ++k) l[k] = 0.0f;
#pragma unroll
    for (int jj = 0; jj < TT; ++jj){
        float vij = sv[i][jj];
#pragma unroll
        for (int k = 0; k < TT; ++k) l[k] = fmaf(vij, ss[b][jj][k], l[k]);
    }
#pragma unroll
    for (int k = 0; k < TT; ++k) sl[tid][k] = l[k];
    __syncthreads();
    if (tid < TT){
        float s = 0.0f, s2 = 0.0f;
        for (int r = 0; r < 192; ++r){ float x = sl[r][tid]; s += x; s2 = fmaf(x, x, s2); }
        float m = s * (1.0f/192.0f);
        smean[tid] = m;
        sinv[tid]  = rsqrtf(s2 * (1.0f/192.0f) - m*m + 1e-5f);
    }
    __syncthreads();
    float mx = -3.4e38f;
#pragma unroll
    for (int k = 0; k < TT; ++k){
        float y = (l[k] - smean[k]) * sinv[k] * gamma[k] + beta[k];
        if ((i < 12) != (k < 12)) y -= 1e13f;
        l[k] = y;
        mx = fmaxf(mx, y);
    }
    float s = 0.0f;
#pragma unroll
    for (int k = 0; k < TT; ++k){ float e = __expf(l[k] - mx); l[k] = e; s += e; }
    float inv = 1.0f / s;
#pragma unroll
    for (int k = 0; k < TT; ++k)
        out[((size_t)b*TT + i)*TT + k] = l[k] * inv;
}

// ---------------- launch ----------------
extern "C" void kernel_launch(void* const* d_in, const int* in_sizes, int n_in,
                              void* d_out, int out_size){
    const float* seq   = (const float*)d_in[0];
    const float* w1    = (const float*)d_in[1];
    const float* w2    = (const float*)d_in[2];
    const float* Wd1   = (const float*)d_in[3];
    const float* Wd2   = (const float*)d_in[4];
    const float* w     = (const float*)d_in[5];
    const float* bbias = (const float*)d_in[6];
    const float* v     = (const float*)d_in[7];
    const float* gamma = (const float*)d_in[8];
    const float* beta  = (const float*)d_in[9];
    float* out = (float*)d_out;

    cudaFuncSetAttribute(k1_reduce, cudaFuncAttributeMaxDynamicSharedMemorySize, K1_SMEM);

    k0_zero   <<<(BB*TT*NNODES + 255)/256, 256>>>();
    k1_reduce <<<256, 192, K1_SMEM>>>(seq, w1, w2);
    k2a_conv1 <<<BB*16, 256>>>(Wd1);
    k2b_conv2 <<<256, 256>>>(Wd2);
    k2c_gemm  <<<512, 192>>>(w);
    k2d1_attn <<<BB*TT, 128>>>(bbias);
    k2d2_final<<<1, 192>>>(v, gamma, beta, out);
}

// round 10
// speedup vs baseline: 1.4005x; 1.4005x over previous
#include <cuda_runtime.h>
#include <cstdint>

#define BB 8
#define CC 512
#define NNODES 2048
#define TT 24

#define K1_PITCH 192                       // words per c-row (768 B)
#define K1_TILE  (128*K1_PITCH)            // words per buffer
#define K1_SMEM  ((2*K1_TILE + 192) * 4)   // two buffers + w1/w2 slices (bytes)

typedef unsigned long long ull;

// ---------------- scratch (static device arrays; no allocation) ----------------
__device__ float g_f1  [BB*TT*NNODES];   // f1[b][t][n]          (atomically accumulated)
__device__ float g_f1c [BB*TT*NNODES];   // dilated conv of f1
__device__ float g_f2  [BB*CC*TT];       // f2[b][c][t]          (atomically accumulated)
__device__ float g_f2cT[BB*TT*CC];       // f2c transposed [b][t][c]   (atomically accumulated)
__device__ float g_g   [BB*TT*CC];       // g[b][t][c] = f1c @ w       (atomically accumulated)
__device__ float g_s   [BB*TT*TT];       // sigmoid attention matrix

// ---------------- packed f32x2 helpers ----------------
__device__ __forceinline__ ull fma2(ull a, ull b, ull c){
    ull d;
    asm("fma.rn.f32x2 %0, %1, %2, %3;" : "=l"(d) : "l"(a), "l"(b), "l"(c));
    return d;
}
__device__ __forceinline__ ull add2(ull a, ull b){
    ull d;
    asm("add.rn.f32x2 %0, %1, %2;" : "=l"(d) : "l"(a), "l"(b));
    return d;
}
__device__ __forceinline__ ull pack2(float f){
    ull r;
    asm("mov.b64 %0, {%1, %1};" : "=l"(r) : "f"(f));
    return r;
}
__device__ __forceinline__ float2 unpk2(ull v){
    float2 f;
    asm("mov.b64 {%0, %1}, %2;" : "=f"(f.x), "=f"(f.y) : "l"(v));
    return f;
}

// ---------------- K0: zero accumulated scratch ----------------
__global__ void k0_zero(){
    int idx = blockIdx.x * 256 + threadIdx.x;
    if (idx < BB*TT*NNODES) g_f1[idx] = 0.0f;
    if (idx < BB*CC*TT){
        g_f2  [idx] = 0.0f;
        g_f2cT[idx] = 0.0f;
        g_g   [idx] = 0.0f;
    }
}

// ---------------- K1: fused dual weighted reduction over seq ----------------
// grid = 8b x 4ct x 32ns = 1024 blocks, block = 192, 1 block/SM.
// cp.async double-buffered chunks of (128c x 8n x 24t); XOR-swizzled smem tile
// (16B units, u ^ (c&7)) -> conflict-free staging stores, f2 LDS.128, f1 LDS.32.
__device__ __forceinline__ void k1_stage(const float* gbase, float* buf, int ju, int c0s){
#pragma unroll
    for (int k2 = 0; k2 < 32; ++k2){
        const int c = c0s + 4*k2;
        const float* g = gbase + (size_t)c * (NNODES*TT);
        unsigned sa = (unsigned)__cvta_generic_to_shared(
            &buf[c*K1_PITCH + ((ju ^ (c & 7)) << 2)]);
        asm volatile("cp.async.cg.shared.global [%0], [%1], 16;" :: "r"(sa), "l"(g) : "memory");
    }
    asm volatile("cp.async.commit_group;" ::: "memory");
}

__global__ void __launch_bounds__(192, 1)
k1_reduce(const float* __restrict__ seq, const float* __restrict__ w1, const float* __restrict__ w2){
    extern __shared__ float sm[];
    float* buf0 = sm;
    float* buf1 = sm + K1_TILE;
    float* sw1  = sm + 2*K1_TILE;      // [128]
    float* sw2n = sw1 + 128;           // [64]

    const int blk = blockIdx.x;
    const int b   = blk >> 7;          // 0..7
    const int ct  = (blk >> 5) & 3;    // c-tile 0..3
    const int ns  = blk & 31;          // n-sweep 0..31 (64 n each)
    const int nb  = ns * 64;
    const int tid = threadIdx.x;
    const int w   = tid >> 5;          // warp -> t-quad (f2 phase)
    const int lane= tid & 31;
    const int ju  = tid % 48;          // float4 unit within c-row segment
    const int c0s = tid / 48;          // 0..3

    if (tid < 128) sw1[tid]       = w1[ct*128 + tid];
    else           sw2n[tid-128]  = w2[nb + tid - 128];

    const float* seqbase = seq + ((size_t)(b*CC + ct*128) * NNODES + nb) * TT + ju*4;

    ull acc[4][2];
#pragma unroll
    for (int kk = 0; kk < 4; ++kk){ acc[kk][0] = 0ull; acc[kk][1] = 0ull; }

    const int xm = lane & 7;

    k1_stage(seqbase, buf0, ju, c0s);

    for (int ch = 0; ch < 8; ++ch){
        float* cur = (ch & 1) ? buf1 : buf0;
        if (ch < 7){
            k1_stage(seqbase + (size_t)(ch+1)*8*TT, (ch & 1) ? buf0 : buf1, ju, c0s);
            asm volatile("cp.async.wait_group 1;" ::: "memory");
        } else {
            asm volatile("cp.async.wait_group 0;" ::: "memory");
        }
        __syncthreads();

        // ---- f2 phase: lane <-> c (4 groups), warp <-> t-quad ----
#pragma unroll
        for (int nn = 0; nn < 8; ++nn){
            const ull w2p = pack2(sw2n[ch*8 + nn]);
            const int u = 6*nn + w;
            const int so = ((u ^ xm) << 2);
#pragma unroll
            for (int kk = 0; kk < 4; ++kk){
                const ulonglong2 x = *reinterpret_cast<const ulonglong2*>(
                    &cur[(lane + 32*kk)*K1_PITCH + so]);
                acc[kk][0] = fma2(w2p, x.x, acc[kk][0]);
                acc[kk][1] = fma2(w2p, x.y, acc[kk][1]);
            }
        }

        // ---- f1 phase: thread <-> (nn, t), serial c with broadcast w1 ----
        {
            const int u0 = tid >> 2, r = tid & 3;
            float v0 = 0.f, v1 = 0.f, v2 = 0.f, v3 = 0.f;
#pragma unroll 4
            for (int c = 0; c < 128; c += 4){
                v0 = fmaf(sw1[c  ], cur[(c  )*K1_PITCH + ((u0 ^ ((c  ) & 7)) << 2) + r], v0);
                v1 = fmaf(sw1[c+1], cur[(c+1)*K1_PITCH + ((u0 ^ ((c+1) & 7)) << 2) + r], v1);
                v2 = fmaf(sw1[c+2], cur[(c+2)*K1_PITCH + ((u0 ^ ((c+2) & 7)) << 2) + r], v2);
                v3 = fmaf(sw1[c+3], cur[(c+3)*K1_PITCH + ((u0 ^ ((c+3) & 7)) << 2) + r], v3);
            }
            const int nn = tid / 24, t = tid - nn*24;
            atomicAdd(&g_f1[((size_t)b*TT + t)*NNODES + nb + ch*8 + nn], (v0 + v1) + (v2 + v3));
        }
        __syncthreads();
    }

    // ---- flush f2 (register-resident across the 64-n sweep) ----
#pragma unroll
    for (int kk = 0; kk < 4; ++kk){
        const int c = ct*128 + lane + 32*kk;
        float* o = g_f2 + ((size_t)b*CC + c)*TT + w*4;
        float2 a = unpk2(acc[kk][0]), d = unpk2(acc[kk][1]);
        atomicAdd(o + 0, a.x);
        atomicAdd(o + 1, a.y);
        atomicAdd(o + 2, d.x);
        atomicAdd(o + 3, d.y);
    }
}

// ---------------- K2a: dilated conv of f1 over the n axis ----------------
__global__ void k2a_conv1(const float* __restrict__ Wd1){
    const int b  = blockIdx.x >> 4;
    const int n0 = (blockIdx.x & 15) * 128;
    __shared__ float s1[TT][130];
    __shared__ float sw[TT][48];
    for (int idx = threadIdx.x; idx < TT*48; idx += 256)
        ((float*)sw)[idx] = Wd1[idx];
    for (int idx = threadIdx.x; idx < TT*130; idx += 256){
        int i = idx / 130, jj = idx % 130;
        int n = n0 + jj - 1;
        s1[i][jj] = (n >= 0 && n < NNODES) ? g_f1[((size_t)b*TT + i)*NNODES + n] : 0.0f;
    }
    __syncthreads();
#pragma unroll
    for (int u = 0; u < 12; ++u){
        int idx = threadIdx.x + u*256;
        int t = idx >> 7, nl = idx & 127;
        float acc = 0.0f;
#pragma unroll
        for (int i = 0; i < TT; ++i)
            acc += s1[i][nl] * sw[t][2*i] + s1[i][nl+2] * sw[t][2*i+1];
        g_f1c[((size_t)b*TT + t)*NNODES + n0 + nl] = acc;
    }
}

// ---------------- K2b: dilated conv of f2 over the t axis (K-split GEMM) ----------------
__global__ void __launch_bounds__(256) k2b_conv2(const float* __restrict__ Wd2){
    const int o0 = (blockIdx.x & 15) * 32;
    const int i0 = (blockIdx.x >> 4) * 32;
    const int tid   = threadIdx.x;
    const int olane = tid & 31;
    const int b     = tid >> 5;

    __shared__ __align__(16) float  sf[32][8][26];
    __shared__ float2 sw2[32][33];

    {
        int i = tid >> 3, bb = tid & 7;
        sf[i][bb][0] = 0.0f; sf[i][bb][25] = 0.0f;
    }
#pragma unroll
    for (int u = 0; u < 24; ++u){
        int idx = tid + u*256;
        int i = idx / 192, r = idx % 192;
        int bb = r / 24, t = r % 24;
        sf[i][bb][t+1] = g_f2[((size_t)bb*CC + i0 + i)*TT + t];
    }
    const float2* wsrc = reinterpret_cast<const float2*>(Wd2);
#pragma unroll
    for (int u = 0; u < 4; ++u){
        int idx = tid + u*256;
        int oo = idx >> 5, iz = idx & 31;
        sw2[oo][iz] = wsrc[(size_t)(o0+oo)*CC + i0 + iz];
    }
    __syncthreads();

    ull acc[12];
#pragma unroll
    for (int u = 0; u < 12; ++u) acc[u] = 0ull;
#pragma unroll 4
    for (int iz = 0; iz < 32; ++iz){
        float2 wv = sw2[olane][iz];
        ull wx = pack2(wv.x), wy = pack2(wv.y);
        const ull* R = reinterpret_cast<const ull*>(&sf[iz][b][0]);
#pragma unroll
        for (int u = 0; u < 12; ++u){
            acc[u] = fma2(wx, R[u], acc[u]);
            acc[u] = fma2(wy, R[u+1], acc[u]);
        }
    }
    float* ob = g_f2cT + (size_t)b*TT*CC + o0 + olane;
#pragma unroll
    for (int u = 0; u < 12; ++u){
        float2 r = unpk2(acc[u]);
        atomicAdd(&ob[(2*u  )*CC], r.x);
        atomicAdd(&ob[(2*u+1)*CC], r.y);
    }
}

// ---------------- K2c: g[b,t,c] += sum_n f1c[b,t,n] * w[n,c]  (K-split x4) ----------------
__global__ void __launch_bounds__(192) k2c_gemm(const float* __restrict__ w){
    const int b  = blockIdx.x >> 6;
    const int c0 = ((blockIdx.x >> 2) & 15) * 32;
    const int ks = blockIdx.x & 3;
    const int tid = threadIdx.x;
    const int tq = tid >> 3;
    const int cq = tid & 7;
    __shared__ __align__(16) float sA[TT*129];
    __shared__ __align__(16) float sB[128*36];
    ull acc[2] = {0ull, 0ull};
    for (int kt = 0; kt < 4; ++kt){
        const int n0 = ks*512 + kt*128;
        for (int idx = tid; idx < 3072; idx += 192){
            int r = idx >> 7, col = idx & 127;
            sA[r*129 + col] = g_f1c[((size_t)b*TT + r)*NNODES + n0 + col];
        }
        for (int idx = tid; idx < 4096; idx += 192){
            int r = idx >> 5, cl = idx & 31;
            sB[r*36 + cl] = w[(size_t)(n0 + r)*CC + c0 + cl];
        }
        __syncthreads();
#pragma unroll 8
        for (int r = 0; r < 128; ++r){
            ull a0 = pack2(sA[tq*129 + r]);
            ulonglong2 bv = *reinterpret_cast<const ulonglong2*>(&sB[r*36 + cq*4]);
            acc[0] = fma2(a0, bv.x, acc[0]);
            acc[1] = fma2(a0, bv.y, acc[1]);
        }
        __syncthreads();
    }
    float2 r0 = unpk2(acc[0]), r1 = unpk2(acc[1]);
    float* o0 = g_g + ((size_t)b*TT + tq)*CC + c0 + cq*4;
    atomicAdd(&o0[0], r0.x);
    atomicAdd(&o0[1], r0.y);
    atomicAdd(&o0[2], r1.x);
    atomicAdd(&o0[3], r1.y);
}

// ---------------- K2d1: s[b,j,k] = sigmoid(g[b,j,:] . f2cT[b,k,:] + bias) ----------------
__global__ void __launch_bounds__(128) k2d1_attn(const float* __restrict__ bbias){
    const int b = blockIdx.x / 24;
    const int jj = blockIdx.x % 24;
    const int tid  = threadIdx.x;
    const int wrp  = tid >> 5;
    const int lane = tid & 31;
    __shared__ __align__(16) float sg[CC];
    const float* grow = g_g + ((size_t)b*TT + jj)*CC;
#pragma unroll
    for (int u = 0; u < 4; ++u) sg[tid + u*128] = grow[tid + u*128];
    __syncthreads();
    const ull* sg2 = reinterpret_cast<const ull*>(sg);
    const ull* f0  = reinterpret_cast<const ull*>(g_f2cT + ((size_t)b*TT + wrp*6)*CC);
    ull acc[6] = {0ull,0ull,0ull,0ull,0ull,0ull};
#pragma unroll
    for (int it = 0; it < 8; ++it){
        ull gv = sg2[lane + it*32];
#pragma unroll
        for (int kk = 0; kk < 6; ++kk)
            acc[kk] = fma2(f0[(size_t)kk*256 + lane + it*32], gv, acc[kk]);
    }
#pragma unroll
    for (int kk = 0; kk < 6; ++kk)
#pragma unroll
        for (int off = 16; off > 0; off >>= 1)
            acc[kk] = add2(acc[kk], __shfl_xor_sync(0xffffffffu, acc[kk], off));
    if (lane < 6){
        int k = wrp*6 + lane;
        float2 aa = unpk2(acc[lane]);
        float sv = aa.x + aa.y + bbias[jj*TT + k];
        g_s[((size_t)b*TT + jj)*TT + k] = 1.0f/(1.0f + __expf(-sv));
    }
}

// ---------------- K2d2: l = v @ s; BN + mask + softmax (single block) ----------------
__global__ void k2d2_final(const float* __restrict__ v, const float* __restrict__ gamma,
                           const float* __restrict__ beta, float* __restrict__ out){
    const int tid = threadIdx.x;
    __shared__ float ss[BB][TT][TT];
    __shared__ float sv[TT][TT];
    __shared__ float sl[192][25];
    __shared__ float smean[TT], sinv[TT];
    for (int idx = tid; idx < BB*TT*TT; idx += 192) ((float*)ss)[idx] = g_s[idx];
    for (int idx = tid; idx < TT*TT;   idx += 192) ((float*)sv)[idx] = v[idx];
    __syncthreads();
    const int b = tid / TT, i = tid % TT;
    float l[TT];
#pragma unroll
    for (int k = 0; k < TT; ++k) l[k] = 0.0f;
#pragma unroll
    for (int jj = 0; jj < TT; ++jj){
        float vij = sv[i][jj];
#pragma unroll
        for (int k = 0; k < TT; ++k) l[k] = fmaf(vij, ss[b][jj][k], l[k]);
    }
#pragma unroll
    for (int k = 0; k < TT; ++k) sl[tid][k] = l[k];
    __syncthreads();
    if (tid < TT){
        float s = 0.0f, s2 = 0.0f;
        for (int r = 0; r < 192; ++r){ float x = sl[r][tid]; s += x; s2 = fmaf(x, x, s2); }
        float m = s * (1.0f/192.0f);
        smean[tid] = m;
        sinv[tid]  = rsqrtf(s2 * (1.0f/192.0f) - m*m + 1e-5f);
    }
    __syncthreads();
    float mx = -3.4e38f;
#pragma unroll
    for (int k = 0; k < TT; ++k){
        float y = (l[k] - smean[k]) * sinv[k] * gamma[k] + beta[k];
        if ((i < 12) != (k < 12)) y -= 1e13f;
        l[k] = y;
        mx = fmaxf(mx, y);
    }
    float s = 0.0f;
#pragma unroll
    for (int k = 0; k < TT; ++k){ float e = __expf(l[k] - mx); l[k] = e; s += e; }
    float inv = 1.0f / s;
#pragma unroll
    for (int k = 0; k < TT; ++k)
        out[((size_t)b*TT + i)*TT + k] = l[k] * inv;
}

// ---------------- launch ----------------
extern "C" void kernel_launch(void* const* d_in, const int* in_sizes, int n_in,
                              void* d_out, int out_size){
    const float* seq   = (const float*)d_in[0];
    const float* w1    = (const float*)d_in[1];
    const float* w2    = (const float*)d_in[2];
    const float* Wd1   = (const float*)d_in[3];
    const float* Wd2   = (const float*)d_in[4];
    const float* w     = (const float*)d_in[5];
    const float* bbias = (const float*)d_in[6];
    const float* v     = (const float*)d_in[7];
    const float* gamma = (const float*)d_in[8];
    const float* beta  = (const float*)d_in[9];
    float* out = (float*)d_out;

    cudaFuncSetAttribute(k1_reduce, cudaFuncAttributeMaxDynamicSharedMemorySize, K1_SMEM);

    k0_zero   <<<(BB*TT*NNODES + 255)/256, 256>>>();
    k1_reduce <<<1024, 192, K1_SMEM>>>(seq, w1, w2);
    k2a_conv1 <<<BB*16, 256>>>(Wd1);
    k2b_conv2 <<<256, 256>>>(Wd2);
    k2c_gemm  <<<512, 192>>>(w);
    k2d1_attn <<<BB*TT, 128>>>(bbias);
    k2d2_final<<<1, 192>>>(v, gamma, beta, out);
}